// round 1
// baseline (speedup 1.0000x reference)
#include <cuda_runtime.h>
#include <cuda_bf16.h>
#include <math.h>

// Problem constants
#define Bc 2
#define Sc 2048
#define Cc 1280
#define Hc 20
#define Dc 64
#define Rc 16
#define Mrows (Bc*Sc)          // 4096
#define QSCALE 0.125f          // 1/sqrt(64)

// ------------------------- device scratch (no allocs allowed) ---------------
__device__ float g_Wq[Cc*Cc];
__device__ float g_Wk[Cc*Cc];
__device__ float g_Wv[Cc*Cc];
__device__ float g_Wo[Cc*Cc];
__device__ float g_q[Mrows*Cc];
__device__ float g_k[Mrows*Cc];
__device__ float g_v[Mrows*Cc];
__device__ float g_oacc[Mrows*Cc];

// ------------------------- fuse LoRA into dense weight ----------------------
// Weff[o][c] = W[o][c] + sum_r Bup[o][r] * A[r][c]
__global__ void fuse_w_kernel(const float* __restrict__ W,
                              const float* __restrict__ A,
                              const float* __restrict__ Bup,
                              float* __restrict__ out) {
    int idx = blockIdx.x * blockDim.x + threadIdx.x;
    if (idx >= Cc*Cc) return;
    int o = idx / Cc;
    int c = idx - o * Cc;
    float acc = W[idx];
#pragma unroll
    for (int r = 0; r < Rc; r++)
        acc += Bup[o*Rc + r] * A[r*Cc + c];
    out[idx] = acc;
}

// ------------------------- GEMM: Y = X @ W^T (+bias) ------------------------
// X: [M,K] row-major, W: [N,K] row-major, Y: [M,N].
// 128x128 tile, BK=16, 256 threads, 8x8 per thread (split 4+4).
#define BM 128
#define BN 128
#define BK 16
__global__ __launch_bounds__(256) void gemm_xwt_kernel(
    const float* __restrict__ X, const float* __restrict__ W,
    const float* __restrict__ bias, float* __restrict__ Y,
    int M, int N, int K) {
    __shared__ float Xs[BM][BK + 1];
    __shared__ float Ws[BN][BK + 1];

    int tid = threadIdx.x;
    int tx = tid & 15;       // 0..15 -> cols
    int ty = tid >> 4;       // 0..15 -> rows
    int m0 = blockIdx.y * BM;
    int n0 = blockIdx.x * BN;

    float acc[8][8];
#pragma unroll
    for (int i = 0; i < 8; i++)
#pragma unroll
        for (int j = 0; j < 8; j++) acc[i][j] = 0.f;

    for (int k0 = 0; k0 < K; k0 += BK) {
        // load tiles with float4 (BM*BK/4 = 512 vectors, 2 per thread)
#pragma unroll
        for (int e = tid; e < BM * 4; e += 256) {
            int r = e >> 2;
            int c4 = (e & 3) << 2;
            float4 t = *(const float4*)&X[(size_t)(m0 + r) * K + k0 + c4];
            Xs[r][c4 + 0] = t.x; Xs[r][c4 + 1] = t.y;
            Xs[r][c4 + 2] = t.z; Xs[r][c4 + 3] = t.w;
        }
#pragma unroll
        for (int e = tid; e < BN * 4; e += 256) {
            int r = e >> 2;
            int c4 = (e & 3) << 2;
            float4 t = *(const float4*)&W[(size_t)(n0 + r) * K + k0 + c4];
            Ws[r][c4 + 0] = t.x; Ws[r][c4 + 1] = t.y;
            Ws[r][c4 + 2] = t.z; Ws[r][c4 + 3] = t.w;
        }
        __syncthreads();

#pragma unroll
        for (int kk = 0; kk < BK; kk++) {
            float a[8], b[8];
#pragma unroll
            for (int u = 0; u < 4; u++) {
                a[u]     = Xs[ty * 4 + u][kk];
                a[4 + u] = Xs[64 + ty * 4 + u][kk];
                b[u]     = Ws[tx * 4 + u][kk];
                b[4 + u] = Ws[64 + tx * 4 + u][kk];
            }
#pragma unroll
            for (int i = 0; i < 8; i++)
#pragma unroll
                for (int j = 0; j < 8; j++)
                    acc[i][j] = fmaf(a[i], b[j], acc[i][j]);
        }
        __syncthreads();
    }

    // epilogue
#pragma unroll
    for (int i = 0; i < 8; i++) {
        int row = m0 + ((i < 4) ? (ty * 4 + i) : (64 + ty * 4 + (i - 4)));
#pragma unroll
        for (int j = 0; j < 8; j++) {
            int col = n0 + ((j < 4) ? (tx * 4 + j) : (64 + tx * 4 + (j - 4)));
            float v = acc[i][j];
            if (bias) v += bias[col];
            Y[(size_t)row * N + col] = v;
        }
    }
}

// ------------------------- flash attention ----------------------------------
// grid: (S/64, H, B). 128 threads (ty 0..7, tx 0..15). Per-thread 8 rows x 4 cols.
// Q tile 64x64 resident; loop over 32 KV tiles of 64 rows.
// Dynamic smem: Qs[64*64] + KP[64*65] (K then reused for P) + Vs[64*64]
#define FLASH_SMEM ((64*64 + 64*65 + 64*64) * 4)

__global__ __launch_bounds__(128) void flash_kernel(
    const float* __restrict__ Qg, const float* __restrict__ Kg,
    const float* __restrict__ Vg, float* __restrict__ Og) {
    extern __shared__ float sm[];
    float* Qs = sm;                 // stride 64
    float* KP = sm + 64 * 64;       // stride 65
    float* Vs = KP + 64 * 65;       // stride 64

    int tid = threadIdx.x;
    int tx = tid & 15;
    int ty = tid >> 4;              // 0..7
    int qt = blockIdx.x;
    int h  = blockIdx.y;
    int b  = blockIdx.z;

    const float* Qp = Qg + (size_t)(b * Sc + qt * 64) * Cc + h * Dc;
    const float* Kp = Kg + (size_t)b * Sc * Cc + h * Dc;
    const float* Vp = Vg + (size_t)b * Sc * Cc + h * Dc;

    // load Q tile (64 rows x 64 cols) via float4: 64*16 vectors / 128 thr
#pragma unroll
    for (int e = tid; e < 64 * 16; e += 128) {
        int r = e >> 4;
        int c4 = (e & 15) << 2;
        float4 t = *(const float4*)&Qp[(size_t)r * Cc + c4];
        Qs[r * 64 + c4 + 0] = t.x; Qs[r * 64 + c4 + 1] = t.y;
        Qs[r * 64 + c4 + 2] = t.z; Qs[r * 64 + c4 + 3] = t.w;
    }

    int rows[8];
#pragma unroll
    for (int u = 0; u < 4; u++) { rows[u] = ty * 4 + u; rows[4 + u] = 32 + ty * 4 + u; }

    float m8[8], l8[8], acc[8][4];
#pragma unroll
    for (int i = 0; i < 8; i++) {
        m8[i] = -INFINITY; l8[i] = 0.f;
#pragma unroll
        for (int v = 0; v < 4; v++) acc[i][v] = 0.f;
    }

    for (int kt = 0; kt < Sc / 64; kt++) {
        // load K and V tiles
#pragma unroll
        for (int e = tid; e < 64 * 16; e += 128) {
            int r = e >> 4;
            int c4 = (e & 15) << 2;
            float4 tk = *(const float4*)&Kp[(size_t)(kt * 64 + r) * Cc + c4];
            KP[r * 65 + c4 + 0] = tk.x; KP[r * 65 + c4 + 1] = tk.y;
            KP[r * 65 + c4 + 2] = tk.z; KP[r * 65 + c4 + 3] = tk.w;
            float4 tv = *(const float4*)&Vp[(size_t)(kt * 64 + r) * Cc + c4];
            Vs[r * 64 + c4 + 0] = tv.x; Vs[r * 64 + c4 + 1] = tv.y;
            Vs[r * 64 + c4 + 2] = tv.z; Vs[r * 64 + c4 + 3] = tv.w;
        }
        __syncthreads();

        // S = Q K^T * scale   (per-thread 8x4)
        float s[8][4];
#pragma unroll
        for (int i = 0; i < 8; i++)
#pragma unroll
            for (int v = 0; v < 4; v++) s[i][v] = 0.f;

#pragma unroll 8
        for (int d = 0; d < 64; d++) {
            float a[8], bb[4];
#pragma unroll
            for (int u = 0; u < 4; u++) {
                a[u]     = Qs[(ty * 4 + u) * 64 + d];
                a[4 + u] = Qs[(32 + ty * 4 + u) * 64 + d];
            }
#pragma unroll
            for (int v = 0; v < 4; v++) bb[v] = KP[(tx * 4 + v) * 65 + d];
#pragma unroll
            for (int i = 0; i < 8; i++)
#pragma unroll
                for (int v = 0; v < 4; v++) s[i][v] = fmaf(a[i], bb[v], s[i][v]);
        }

        // online softmax (reduce over the 16 tx lanes sharing each row)
#pragma unroll
        for (int i = 0; i < 8; i++) {
            float mloc = s[i][0];
#pragma unroll
            for (int v = 1; v < 4; v++) mloc = fmaxf(mloc, s[i][v]);
            mloc *= QSCALE;  // scale once; scale s too below
#pragma unroll
            for (int off = 8; off >= 1; off >>= 1)
                mloc = fmaxf(mloc, __shfl_xor_sync(0xffffffffu, mloc, off));
            float mnew = fmaxf(m8[i], mloc);
            float alpha = __expf(m8[i] - mnew);
            float sum = 0.f;
#pragma unroll
            for (int v = 0; v < 4; v++) {
                float p = __expf(s[i][v] * QSCALE - mnew);
                s[i][v] = p;
                sum += p;
            }
#pragma unroll
            for (int off = 8; off >= 1; off >>= 1)
                sum += __shfl_xor_sync(0xffffffffu, sum, off);
            l8[i] = l8[i] * alpha + sum;
            m8[i] = mnew;
#pragma unroll
            for (int v = 0; v < 4; v++) acc[i][v] *= alpha;
        }

        __syncthreads();   // all warps done reading K from KP
        // write P into KP
#pragma unroll
        for (int i = 0; i < 8; i++)
#pragma unroll
            for (int v = 0; v < 4; v++)
                KP[rows[i] * 65 + tx * 4 + v] = s[i][v];
        __syncthreads();

        // O += P V   (inner over j, per-thread 8 rows x 4 d-cols)
#pragma unroll 8
        for (int j = 0; j < 64; j++) {
            float a[8], bb[4];
#pragma unroll
            for (int i = 0; i < 8; i++) a[i] = KP[rows[i] * 65 + j];
#pragma unroll
            for (int v = 0; v < 4; v++) bb[v] = Vs[j * 64 + tx * 4 + v];
#pragma unroll
            for (int i = 0; i < 8; i++)
#pragma unroll
                for (int v = 0; v < 4; v++) acc[i][v] = fmaf(a[i], bb[v], acc[i][v]);
        }
        __syncthreads();   // before next tile overwrites KP/Vs
    }

    // epilogue: normalize and store
#pragma unroll
    for (int i = 0; i < 8; i++) {
        float inv = 1.f / l8[i];
        int grow = b * Sc + qt * 64 + rows[i];
#pragma unroll
        for (int v = 0; v < 4; v++)
            Og[(size_t)grow * Cc + h * Dc + tx * 4 + v] = acc[i][v] * inv;
    }
}

// ------------------------- launch -------------------------------------------
extern "C" void kernel_launch(void* const* d_in, const int* in_sizes, int n_in,
                              void* d_out, int out_size) {
    const float* x  = (const float*)d_in[0];
    const float* Wq = (const float*)d_in[1];
    const float* Wk = (const float*)d_in[2];
    const float* Wv = (const float*)d_in[3];
    const float* Wo = (const float*)d_in[4];
    const float* bo = (const float*)d_in[5];
    const float* Aq = (const float*)d_in[6];
    const float* Bq = (const float*)d_in[7];
    const float* Ak = (const float*)d_in[8];
    const float* Bk = (const float*)d_in[9];
    const float* Av = (const float*)d_in[10];
    const float* Bv = (const float*)d_in[11];
    const float* Ao = (const float*)d_in[12];
    const float* Bo = (const float*)d_in[13];
    float* out = (float*)d_out;

    float *pWq, *pWk, *pWv, *pWo, *pq, *pk, *pv, *po;
    cudaGetSymbolAddress((void**)&pWq, g_Wq);
    cudaGetSymbolAddress((void**)&pWk, g_Wk);
    cudaGetSymbolAddress((void**)&pWv, g_Wv);
    cudaGetSymbolAddress((void**)&pWo, g_Wo);
    cudaGetSymbolAddress((void**)&pq, g_q);
    cudaGetSymbolAddress((void**)&pk, g_k);
    cudaGetSymbolAddress((void**)&pv, g_v);
    cudaGetSymbolAddress((void**)&po, g_oacc);

    // 1) fold LoRA into dense weights
    int fw_blocks = (Cc * Cc + 255) / 256;
    fuse_w_kernel<<<fw_blocks, 256>>>(Wq, Aq, Bq, pWq);
    fuse_w_kernel<<<fw_blocks, 256>>>(Wk, Ak, Bk, pWk);
    fuse_w_kernel<<<fw_blocks, 256>>>(Wv, Av, Bv, pWv);
    fuse_w_kernel<<<fw_blocks, 256>>>(Wo, Ao, Bo, pWo);

    // 2) q/k/v projections
    dim3 ggrid(Cc / BN, Mrows / BM);   // (10, 32)
    gemm_xwt_kernel<<<ggrid, 256>>>(x, pWq, nullptr, pq, Mrows, Cc, Cc);
    gemm_xwt_kernel<<<ggrid, 256>>>(x, pWk, nullptr, pk, Mrows, Cc, Cc);
    gemm_xwt_kernel<<<ggrid, 256>>>(x, pWv, nullptr, pv, Mrows, Cc, Cc);

    // 3) flash attention
    cudaFuncSetAttribute(flash_kernel,
                         cudaFuncAttributeMaxDynamicSharedMemorySize, FLASH_SMEM);
    dim3 fgrid(Sc / 64, Hc, Bc);       // (32, 20, 2)
    flash_kernel<<<fgrid, 128, FLASH_SMEM>>>(pq, pk, pv, po);

    // 4) output projection (+bias) -> d_out
    gemm_xwt_kernel<<<ggrid, 256>>>(po, pWo, bo, out, Mrows, Cc, Cc);
}

// round 2
// speedup vs baseline: 3.2488x; 3.2488x over previous
#include <cuda_runtime.h>
#include <cuda_bf16.h>
#include <math.h>

// Problem constants
#define Bc 2
#define Sc 2048
#define Cc 1280
#define Hc 20
#define Dc 64
#define Rc 16
#define Mrows (Bc*Sc)          // 4096
#define QSCALE 0.125f          // 1/sqrt(64)

// ------------------------- device scratch (no allocs allowed) ---------------
__device__ float g_Wq[Cc*Cc];
__device__ float g_Wk[Cc*Cc];
__device__ float g_Wv[Cc*Cc];
__device__ float g_Wo[Cc*Cc];
__device__ float g_q[Mrows*Cc];
__device__ float g_k[Mrows*Cc];
__device__ float g_v[Mrows*Cc];
__device__ float g_oacc[Mrows*Cc];

// ------------------------- tf32 helpers -------------------------------------
__device__ __forceinline__ unsigned f2tf32(float f) {
    unsigned u;
    asm("cvt.rna.tf32.f32 %0, %1;" : "=r"(u) : "f"(f));
    return u;
}

// D += A * B, m16n8k8, A row-major tf32, B col-major tf32, fp32 accum
__device__ __forceinline__ void mma_tf32(float* d, const unsigned* a, const unsigned* b) {
    asm("mma.sync.aligned.m16n8k8.row.col.f32.tf32.tf32.f32 "
        "{%0,%1,%2,%3}, {%4,%5,%6,%7}, {%8,%9}, {%0,%1,%2,%3};"
        : "+f"(d[0]), "+f"(d[1]), "+f"(d[2]), "+f"(d[3])
        : "r"(a[0]), "r"(a[1]), "r"(a[2]), "r"(a[3]), "r"(b[0]), "r"(b[1]));
}

// ------------------------- fuse LoRA into dense weights (all 4 at once) -----
__global__ void fuse_all_kernel(
    const float* __restrict__ Wq, const float* __restrict__ Aq, const float* __restrict__ Bq,
    const float* __restrict__ Wk, const float* __restrict__ Ak, const float* __restrict__ Bk,
    const float* __restrict__ Wv, const float* __restrict__ Av, const float* __restrict__ Bv,
    const float* __restrict__ Wo, const float* __restrict__ Ao, const float* __restrict__ Bo,
    float* __restrict__ oq, float* __restrict__ ok,
    float* __restrict__ ov, float* __restrict__ oo) {
    int idx = blockIdx.x * blockDim.x + threadIdx.x;
    if (idx >= Cc*Cc) return;
    const float *W, *A, *Bup; float* out;
    switch (blockIdx.y) {
        case 0: W = Wq; A = Aq; Bup = Bq; out = oq; break;
        case 1: W = Wk; A = Ak; Bup = Bk; out = ok; break;
        case 2: W = Wv; A = Av; Bup = Bv; out = ov; break;
        default: W = Wo; A = Ao; Bup = Bo; out = oo; break;
    }
    int o = idx / Cc;
    int c = idx - o * Cc;
    float acc = W[idx];
#pragma unroll
    for (int r = 0; r < Rc; r++)
        acc += Bup[o*Rc + r] * A[r*Cc + c];
    out[idx] = acc;
}

// ------------------------- tf32 GEMM: Y = X @ W^T (+bias) -------------------
// X: [M,K] row-major, W: [N,K] row-major, Y: [M,N].
// Block tile 128x128, BK=32, 256 threads (8 warps, 2m x 4n), warp tile 64x32.
// Per warp: 4 m-tiles (16) x 4 n-tiles (8) of m16n8k8.
#define XST 36   // smem row stride (floats): (4*row + col) % 32 conflict-free
__global__ __launch_bounds__(256) void gemm_tf32_kernel(
    const float* __restrict__ X,
    const float* __restrict__ W0, const float* __restrict__ W1, const float* __restrict__ W2,
    const float* __restrict__ bias,
    float* __restrict__ Y0, float* __restrict__ Y1, float* __restrict__ Y2,
    int M, int N, int K) {
    __shared__ unsigned Xs[128 * XST];
    __shared__ unsigned Ws[128 * XST];

    const float* W = (blockIdx.z == 0) ? W0 : (blockIdx.z == 1) ? W1 : W2;
    float* Y       = (blockIdx.z == 0) ? Y0 : (blockIdx.z == 1) ? Y1 : Y2;

    int tid = threadIdx.x;
    int lane = tid & 31, wid = tid >> 5;
    int g = lane >> 2, t = lane & 3;
    int wm = wid & 1, wn = wid >> 1;           // warp coords: 2 x 4
    int m0 = blockIdx.y * 128, n0 = blockIdx.x * 128;

    float acc[4][4][4];
#pragma unroll
    for (int i = 0; i < 4; i++)
#pragma unroll
        for (int j = 0; j < 4; j++)
#pragma unroll
            for (int u = 0; u < 4; u++) acc[i][j][u] = 0.f;

    for (int k0 = 0; k0 < K; k0 += 32) {
        // load 128x32 X and W tiles; convert to tf32 on store
#pragma unroll
        for (int e = tid; e < 128 * 8; e += 256) {
            int r = e >> 3, c4 = (e & 7) << 2;
            float4 xv = *(const float4*)&X[(size_t)(m0 + r) * K + k0 + c4];
            unsigned* p = &Xs[r * XST + c4];
            p[0] = f2tf32(xv.x); p[1] = f2tf32(xv.y);
            p[2] = f2tf32(xv.z); p[3] = f2tf32(xv.w);
            float4 wv = *(const float4*)&W[(size_t)(n0 + r) * K + k0 + c4];
            unsigned* q = &Ws[r * XST + c4];
            q[0] = f2tf32(wv.x); q[1] = f2tf32(wv.y);
            q[2] = f2tf32(wv.z); q[3] = f2tf32(wv.w);
        }
        __syncthreads();

#pragma unroll
        for (int kc = 0; kc < 4; kc++) {
            int kb = kc * 8;
            unsigned a[4][4], b[4][2];
#pragma unroll
            for (int mt = 0; mt < 4; mt++) {
                int rb = wm * 64 + mt * 16;
                a[mt][0] = Xs[(rb + g)     * XST + kb + t];
                a[mt][1] = Xs[(rb + g + 8) * XST + kb + t];
                a[mt][2] = Xs[(rb + g)     * XST + kb + t + 4];
                a[mt][3] = Xs[(rb + g + 8) * XST + kb + t + 4];
            }
#pragma unroll
            for (int nt = 0; nt < 4; nt++) {
                int nb = wn * 32 + nt * 8;
                b[nt][0] = Ws[(nb + g) * XST + kb + t];
                b[nt][1] = Ws[(nb + g) * XST + kb + t + 4];
            }
#pragma unroll
            for (int mt = 0; mt < 4; mt++)
#pragma unroll
                for (int nt = 0; nt < 4; nt++)
                    mma_tf32(acc[mt][nt], a[mt], b[nt]);
        }
        __syncthreads();
    }

    // epilogue: d0,d1 at (row, 2t..2t+1); d2,d3 at (row+8, same cols)
#pragma unroll
    for (int mt = 0; mt < 4; mt++) {
        int row = m0 + wm * 64 + mt * 16 + g;
#pragma unroll
        for (int nt = 0; nt < 4; nt++) {
            int col = n0 + wn * 32 + nt * 8 + 2 * t;
            float b0 = bias ? bias[col] : 0.f;
            float b1 = bias ? bias[col + 1] : 0.f;
            float2 v0 = make_float2(acc[mt][nt][0] + b0, acc[mt][nt][1] + b1);
            float2 v1 = make_float2(acc[mt][nt][2] + b0, acc[mt][nt][3] + b1);
            *(float2*)&Y[(size_t)row * N + col] = v0;
            *(float2*)&Y[(size_t)(row + 8) * N + col] = v1;
        }
    }
}

// ------------------------- tf32 flash attention ------------------------------
// grid (S/64, H, B), 128 threads = 4 warps; warp owns 16 q-rows.
// Q fragments in registers. K tile stride 68, V stride 72, P stride 68.
#define KST 68
#define VST 72
#define PST 68
#define FLASH_SMEM ((64*KST + 64*VST + 64*PST) * 4)

__global__ __launch_bounds__(128) void flash_tf32_kernel(
    const float* __restrict__ Qg, const float* __restrict__ Kg,
    const float* __restrict__ Vg, float* __restrict__ Og) {
    extern __shared__ unsigned sm[];
    unsigned* Ks = sm;
    unsigned* Vs = sm + 64 * KST;
    unsigned* Ps = Vs + 64 * VST;   // also used as Q staging

    int tid = threadIdx.x;
    int lane = tid & 31, wid = tid >> 5;
    int g = lane >> 2, t = lane & 3;
    int wq = wid * 16;
    int qt = blockIdx.x, h = blockIdx.y, b = blockIdx.z;

    const float* Qp = Qg + (size_t)(b * Sc + qt * 64) * Cc + h * Dc;
    const float* Kp = Kg + (size_t)b * Sc * Cc + h * Dc;
    const float* Vp = Vg + (size_t)b * Sc * Cc + h * Dc;

    // stage Q (64x64) into Ps, convert to tf32
#pragma unroll
    for (int e = tid; e < 64 * 16; e += 128) {
        int r = e >> 4, c4 = (e & 15) << 2;
        float4 v = *(const float4*)&Qp[(size_t)r * Cc + c4];
        unsigned* p = &Ps[r * PST + c4];
        p[0] = f2tf32(v.x); p[1] = f2tf32(v.y);
        p[2] = f2tf32(v.z); p[3] = f2tf32(v.w);
    }
    __syncthreads();

    // Q fragments: 8 k-chunks over D=64
    unsigned qa[8][4];
#pragma unroll
    for (int kc = 0; kc < 8; kc++) {
        int kb = kc * 8;
        qa[kc][0] = Ps[(wq + g)     * PST + kb + t];
        qa[kc][1] = Ps[(wq + g + 8) * PST + kb + t];
        qa[kc][2] = Ps[(wq + g)     * PST + kb + t + 4];
        qa[kc][3] = Ps[(wq + g + 8) * PST + kb + t + 4];
    }
    __syncthreads();

    float m2[2] = {-INFINITY, -INFINITY};
    float l2[2] = {0.f, 0.f};
    float oacc[8][4];
#pragma unroll
    for (int dt = 0; dt < 8; dt++)
#pragma unroll
        for (int u = 0; u < 4; u++) oacc[dt][u] = 0.f;

    for (int kt = 0; kt < Sc / 64; kt++) {
        // load K,V tiles (convert tf32)
#pragma unroll
        for (int e = tid; e < 64 * 16; e += 128) {
            int r = e >> 4, c4 = (e & 15) << 2;
            float4 kv = *(const float4*)&Kp[(size_t)(kt * 64 + r) * Cc + c4];
            unsigned* pk = &Ks[r * KST + c4];
            pk[0] = f2tf32(kv.x); pk[1] = f2tf32(kv.y);
            pk[2] = f2tf32(kv.z); pk[3] = f2tf32(kv.w);
            float4 vv = *(const float4*)&Vp[(size_t)(kt * 64 + r) * Cc + c4];
            unsigned* pv = &Vs[r * VST + c4];
            pv[0] = f2tf32(vv.x); pv[1] = f2tf32(vv.y);
            pv[2] = f2tf32(vv.z); pv[3] = f2tf32(vv.w);
        }
        __syncthreads();

        // S = Q K^T: per warp m16 x n64, k=64
        float sacc[8][4];
#pragma unroll
        for (int nt = 0; nt < 8; nt++)
#pragma unroll
            for (int u = 0; u < 4; u++) sacc[nt][u] = 0.f;

#pragma unroll
        for (int kc = 0; kc < 8; kc++) {
            int kb = kc * 8;
#pragma unroll
            for (int nt = 0; nt < 8; nt++) {
                unsigned bb[2];
                bb[0] = Ks[(nt * 8 + g) * KST + kb + t];
                bb[1] = Ks[(nt * 8 + g) * KST + kb + t + 4];
                mma_tf32(sacc[nt], qa[kc], bb);
            }
        }

        // online softmax per row r=0 (row g) / r=1 (row g+8)
#pragma unroll
        for (int r = 0; r < 2; r++) {
            float mloc = -INFINITY;
#pragma unroll
            for (int nt = 0; nt < 8; nt++)
                mloc = fmaxf(mloc, fmaxf(sacc[nt][2*r], sacc[nt][2*r + 1]));
            mloc = fmaxf(mloc, __shfl_xor_sync(0xffffffffu, mloc, 1));
            mloc = fmaxf(mloc, __shfl_xor_sync(0xffffffffu, mloc, 2));
            float mnew = fmaxf(m2[r], mloc * QSCALE);
            float alpha = __expf(m2[r] - mnew);
            float sum = 0.f;
#pragma unroll
            for (int nt = 0; nt < 8; nt++) {
#pragma unroll
                for (int j = 0; j < 2; j++) {
                    float p = __expf(sacc[nt][2*r + j] * QSCALE - mnew);
                    sacc[nt][2*r + j] = p;
                    sum += p;
                }
            }
            sum += __shfl_xor_sync(0xffffffffu, sum, 1);
            sum += __shfl_xor_sync(0xffffffffu, sum, 2);
            l2[r] = l2[r] * alpha + sum;
            m2[r] = mnew;
#pragma unroll
            for (int dt = 0; dt < 8; dt++) {
                oacc[dt][2*r]     *= alpha;
                oacc[dt][2*r + 1] *= alpha;
            }
        }

        // write P fragments to smem (re-fragment for PV mma)
#pragma unroll
        for (int nt = 0; nt < 8; nt++) {
            int col = nt * 8 + 2 * t;
            uint2 u0 = make_uint2(f2tf32(sacc[nt][0]), f2tf32(sacc[nt][1]));
            uint2 u1 = make_uint2(f2tf32(sacc[nt][2]), f2tf32(sacc[nt][3]));
            *(uint2*)&Ps[(wq + g)     * PST + col] = u0;
            *(uint2*)&Ps[(wq + g + 8) * PST + col] = u1;
        }
        __syncwarp();

        // O += P V: m16 x n64(d), k=64(keys)
#pragma unroll
        for (int kc = 0; kc < 8; kc++) {
            int kb = kc * 8;
            unsigned pa[4];
            pa[0] = Ps[(wq + g)     * PST + kb + t];
            pa[1] = Ps[(wq + g + 8) * PST + kb + t];
            pa[2] = Ps[(wq + g)     * PST + kb + t + 4];
            pa[3] = Ps[(wq + g + 8) * PST + kb + t + 4];
#pragma unroll
            for (int dt = 0; dt < 8; dt++) {
                unsigned bb[2];
                bb[0] = Vs[(kb + t)     * VST + dt * 8 + g];
                bb[1] = Vs[(kb + t + 4) * VST + dt * 8 + g];
                mma_tf32(oacc[dt], pa, bb);
            }
        }
        __syncthreads();   // before next tile overwrites Ks/Vs (and Ps rows)
    }

    // epilogue
#pragma unroll
    for (int r = 0; r < 2; r++) {
        float inv = 1.f / l2[r];
        int grow = b * Sc + qt * 64 + wq + g + 8 * r;
#pragma unroll
        for (int dt = 0; dt < 8; dt++) {
            int col = h * Dc + dt * 8 + 2 * t;
            float2 v = make_float2(oacc[dt][2*r] * inv, oacc[dt][2*r + 1] * inv);
            *(float2*)&Og[(size_t)grow * Cc + col] = v;
        }
    }
}

// ------------------------- launch -------------------------------------------
extern "C" void kernel_launch(void* const* d_in, const int* in_sizes, int n_in,
                              void* d_out, int out_size) {
    const float* x  = (const float*)d_in[0];
    const float* Wq = (const float*)d_in[1];
    const float* Wk = (const float*)d_in[2];
    const float* Wv = (const float*)d_in[3];
    const float* Wo = (const float*)d_in[4];
    const float* bo = (const float*)d_in[5];
    const float* Aq = (const float*)d_in[6];
    const float* Bq = (const float*)d_in[7];
    const float* Ak = (const float*)d_in[8];
    const float* Bk = (const float*)d_in[9];
    const float* Av = (const float*)d_in[10];
    const float* Bv = (const float*)d_in[11];
    const float* Ao = (const float*)d_in[12];
    const float* Bo = (const float*)d_in[13];
    float* out = (float*)d_out;

    float *pWq, *pWk, *pWv, *pWo, *pq, *pk, *pv, *po;
    cudaGetSymbolAddress((void**)&pWq, g_Wq);
    cudaGetSymbolAddress((void**)&pWk, g_Wk);
    cudaGetSymbolAddress((void**)&pWv, g_Wv);
    cudaGetSymbolAddress((void**)&pWo, g_Wo);
    cudaGetSymbolAddress((void**)&pq, g_q);
    cudaGetSymbolAddress((void**)&pk, g_k);
    cudaGetSymbolAddress((void**)&pv, g_v);
    cudaGetSymbolAddress((void**)&po, g_oacc);

    // 1) fold LoRA into dense weights (all four in one launch)
    dim3 fgrid((Cc * Cc + 255) / 256, 4);
    fuse_all_kernel<<<fgrid, 256>>>(Wq, Aq, Bq, Wk, Ak, Bk, Wv, Av, Bv, Wo, Ao, Bo,
                                    pWq, pWk, pWv, pWo);

    // 2) q/k/v projections in one launch (z = which projection)
    dim3 ggrid(Cc / 128, Mrows / 128, 3);   // (10, 32, 3)
    gemm_tf32_kernel<<<ggrid, 256>>>(x, pWq, pWk, pWv, nullptr, pq, pk, pv,
                                     Mrows, Cc, Cc);

    // 3) flash attention (tf32 tensor cores)
    cudaFuncSetAttribute(flash_tf32_kernel,
                         cudaFuncAttributeMaxDynamicSharedMemorySize, FLASH_SMEM);
    dim3 agrid(Sc / 64, Hc, Bc);            // (32, 20, 2)
    flash_tf32_kernel<<<agrid, 128, FLASH_SMEM>>>(pq, pk, pv, po);

    // 4) output projection (+bias) -> d_out
    dim3 ogrid(Cc / 128, Mrows / 128, 1);
    gemm_tf32_kernel<<<ogrid, 256>>>(po, pWo, pWo, pWo, bo, out, out, out,
                                     Mrows, Cc, Cc);
}